// round 1
// baseline (speedup 1.0000x reference)
#include <cuda_runtime.h>
#include <cstddef>

#define PYR    40000
#define N_PV    2100
#define N_OLM   1800
#define N_BIST  1200
#define N_SEPT   100

// ---- device scratch (no allocations allowed) ----
__device__ float g_pv_raw[N_PV];
__device__ float g_olm_raw[N_OLM];
__device__ float g_bist_raw[N_BIST];
__device__ float g_pv_lat[N_PV];
__device__ float g_olm2pv[N_PV];
__device__ float g_gap[N_PV];
__device__ float g_olm_inh[N_OLM];
__device__ float g_scalars[2];   // [0]=ext_mean, [1]=gain

// ------------------------------------------------------------------
__device__ __forceinline__ float warpReduce(float v) {
    #pragma unroll
    for (int o = 16; o; o >>= 1) v += __shfl_xor_sync(0xffffffffu, v, o);
    return v;
}

// block-wide reduction (256 threads). Result valid on thread 0.
__device__ __forceinline__ float blockReduce256(float v) {
    __shared__ float red[8];
    int lane = threadIdx.x & 31, w = threadIdx.x >> 5;
    v = warpReduce(v);
    if (lane == 0) red[w] = v;
    __syncthreads();
    if (w == 0) {
        v = (lane < 8) ? red[lane] : 0.f;
        v = warpReduce(v);
    }
    return v;
}

// dense block dot: w[0..n) . x[0..n), n % 4 == 0
__device__ __forceinline__ float blockDotF(const float* __restrict__ w,
                                           const float* __restrict__ x, int n) {
    float s = 0.f;
    int n4 = n >> 2;
    const float4* w4 = (const float4*)w;
    const float4* x4 = (const float4*)x;
    for (int i = threadIdx.x; i < n4; i += 256) {
        float4 a = __ldg(w4 + i);
        float4 b = __ldg(x4 + i);
        s += a.x * b.x + a.y * b.y + a.z * b.z + a.w * b.w;
    }
    return blockReduce256(s);
}

// dot against an int32 0/1 spike vector
__device__ __forceinline__ float blockDotSpk(const float* __restrict__ w,
                                             const int* __restrict__ spk, int n) {
    float s = 0.f;
    int n4 = n >> 2;
    const float4* w4 = (const float4*)w;
    const int4*   s4 = (const int4*)spk;
    for (int i = threadIdx.x; i < n4; i += 256) {
        float4 a = __ldg(w4 + i);
        int4   b = __ldg(s4 + i);
        s += (b.x ? a.x : 0.f) + (b.y ? a.y : 0.f) + (b.z ? a.z : 0.f) + (b.w ? a.w : 0.f);
    }
    return blockReduce256(s);
}

// ------------------------------------------------------------------
// Phase A: all input-side matvecs. One block per output row.
//  [0,2100)            pyr_to_pv   @ pyr      -> g_pv_raw
//  [2100,3900)         pyr_to_olm  @ pyr      -> g_olm_raw
//  [3900,5100)         pyr_to_bist @ pyr      -> g_bist_raw
//  [5100,7200)         pv_to_pv    @ prev_pv  -> g_pv_lat
//  [7200,9300)         olm_to_pv   @ prev_olm -> g_olm2pv
//  [9300,11400)        pv_gap      @ prev_vm  -> g_gap
//  [11400,13200)       septal_to_olm @ septal -> g_olm_inh
__global__ void k_phaseA(const float* __restrict__ pyr2pv,
                         const float* __restrict__ pyr2olm,
                         const float* __restrict__ pyr2bist,
                         const int*   __restrict__ pyr_spk,
                         const float* __restrict__ pv2pv,
                         const float* __restrict__ prev_pv,
                         const float* __restrict__ olm2pv,
                         const float* __restrict__ prev_olm,
                         const float* __restrict__ gapW,
                         const float* __restrict__ prev_vm,
                         const float* __restrict__ sept2olm,
                         const float* __restrict__ septal) {
    int b = blockIdx.x;
    float r;
    if (b < N_PV) {
        r = blockDotSpk(pyr2pv + (size_t)b * PYR, pyr_spk, PYR);
        if (threadIdx.x == 0) g_pv_raw[b] = r;
    } else if (b < N_PV + N_OLM) {
        int j = b - N_PV;
        r = blockDotSpk(pyr2olm + (size_t)j * PYR, pyr_spk, PYR);
        if (threadIdx.x == 0) g_olm_raw[j] = r;
    } else if (b < 5100) {
        int j = b - 3900;
        r = blockDotSpk(pyr2bist + (size_t)j * PYR, pyr_spk, PYR);
        if (threadIdx.x == 0) g_bist_raw[j] = r;
    } else if (b < 7200) {
        int j = b - 5100;
        r = blockDotF(pv2pv + (size_t)j * N_PV, prev_pv, N_PV);
        if (threadIdx.x == 0) g_pv_lat[j] = r;
    } else if (b < 9300) {
        int j = b - 7200;
        r = blockDotF(olm2pv + (size_t)j * N_OLM, prev_olm, N_OLM);
        if (threadIdx.x == 0) g_olm2pv[j] = r;
    } else if (b < 11400) {
        int j = b - 9300;
        r = blockDotF(gapW + (size_t)j * N_PV, prev_vm, N_PV);
        if (threadIdx.x == 0) g_gap[j] = r;
    } else {
        int j = b - 11400;
        r = blockDotF(sept2olm + (size_t)j * N_SEPT, septal, N_SEPT);
        if (threadIdx.x == 0) g_olm_inh[j] = r;
    }
}

// ------------------------------------------------------------------
__global__ void k_means(const float* __restrict__ ext) {
    __shared__ float redA[8], redB[8];
    float s1 = 0.f, s2 = 0.f;
    for (int i = threadIdx.x; i < N_PV; i += 256) {
        s1 += ext[i];
        s2 += g_pv_raw[i];
    }
    int lane = threadIdx.x & 31, w = threadIdx.x >> 5;
    s1 = warpReduce(s1);
    s2 = warpReduce(s2);
    if (lane == 0) { redA[w] = s1; redB[w] = s2; }
    __syncthreads();
    if (threadIdx.x == 0) {
        float t1 = 0.f, t2 = 0.f;
        #pragma unroll
        for (int i = 0; i < 8; i++) { t1 += redA[i]; t2 += redB[i]; }
        float ext_mean = t1 / (float)N_PV;
        float drive    = t2 / (float)N_PV;
        float gain = (drive > 0.01f) ? fminf(1.f, drive * 10.f) : 0.f;
        g_scalars[0] = ext_mean;
        g_scalars[1] = gain;
    }
}

// ------------------------------------------------------------------
// LIF updates; spikes written directly into output tail.
__global__ void k_lif(const float* __restrict__ pv_v,
                      const float* __restrict__ olm_v,
                      const float* __restrict__ bist_v,
                      const float* __restrict__ pv_ad,
                      const float* __restrict__ olm_ad,
                      const float* __restrict__ bist_ad,
                      float* __restrict__ out) {
    int i = blockIdx.x * blockDim.x + threadIdx.x;
    float ext_mean = g_scalars[0];
    float gain     = g_scalars[1];
    if (i < N_PV) {
        float g = g_pv_raw[i] + ext_mean * 0.3f
                - g_pv_lat[i] * 0.5f - g_olm2pv[i] * 0.3f
                + g_gap[i] * 0.05f * gain;
        g = fmaxf(g, 0.f);
        float v = pv_v[i];
        float vn = v + (1.f / 7.f) * (-v + g * (3.0f - v));
        out[160000 + i] = (vn >= 2.0f + pv_ad[i]) ? 1.f : 0.f;
    } else if (i < N_PV + N_OLM) {
        int j = i - N_PV;
        float g = fmaxf(g_olm_raw[j] + ext_mean * 0.1f, 0.f);
        float gi = g_olm_inh[j];
        float v = olm_v[j];
        float vn = v + (1.f / 25.f) * (-v + g * (3.0f - v) + gi * (-0.5f - v));
        out[162100 + j] = (vn >= 1.1f + olm_ad[j]) ? 1.f : 0.f;
    } else if (i < 5100) {
        int j = i - 3900;
        float g = fmaxf(g_bist_raw[j] + ext_mean * 0.2f, 0.f);
        float v = bist_v[j];
        float vn = v + (1.f / 12.f) * (-v + g * (3.0f - v));
        out[163900 + j] = (vn >= 0.9f + bist_ad[j]) ? 1.f : 0.f;
    }
}

// ------------------------------------------------------------------
// Output projections: warp-per-pyr-row, spikes staged in shared.
__device__ __forceinline__ float warpDot(const float* __restrict__ w,
                                         const float* __restrict__ xs, int n) {
    float s = 0.f;
    int n4 = n >> 2;
    int lane = threadIdx.x & 31;
    const float4* w4 = (const float4*)w;
    const float4* x4 = (const float4*)xs;
    for (int i = lane; i < n4; i += 32) {
        float4 a = __ldg(w4 + i);
        float4 b = x4[i];
        s += a.x * b.x + a.y * b.y + a.z * b.z + a.w * b.w;
    }
    return warpReduce(s);
}

__global__ void k_out(const float* __restrict__ pv2pyr,
                      const float* __restrict__ gabab,
                      const float* __restrict__ olm2pyr,
                      const float* __restrict__ bist2pyr,
                      float* __restrict__ out) {
    __shared__ float sh[5100];   // pv | olm | bist spikes
    for (int i = threadIdx.x; i < 5100; i += 256) sh[i] = out[160000 + i];
    __syncthreads();
    int warp = threadIdx.x >> 5;
    int row  = blockIdx.x * 8 + warp;
    if (row >= PYR) return;
    const float* shpv = sh;
    const float* sholm = sh + N_PV;
    const float* shbi  = sh + N_PV + N_OLM;
    float peri = warpDot(pv2pyr  + (size_t)row * N_PV,  shpv,  N_PV);
    float pgb  = warpDot(gabab   + (size_t)row * N_PV,  shpv,  N_PV);
    float od   = warpDot(olm2pyr + (size_t)row * N_OLM, sholm, N_OLM);
    float bd   = warpDot(bist2pyr+ (size_t)row * N_BIST, shbi, N_BIST);
    if ((threadIdx.x & 31) == 0) {
        out[row]           = peri;
        out[40000 + row]   = pgb;
        out[80000 + row]   = od + bd;
        out[120000 + row]  = od;
    }
}

// ------------------------------------------------------------------
extern "C" void kernel_launch(void* const* d_in, const int* in_sizes, int n_in,
                              void* d_out, int out_size) {
    const int*   pyr_spikes   = (const int*)  d_in[0];
    const float* septal_gaba  = (const float*)d_in[1];
    const float* external_exc = (const float*)d_in[2];
    const float* prev_pv_spk  = (const float*)d_in[3];
    const float* prev_olm_spk = (const float*)d_in[4];
    const float* prev_pv_vm   = (const float*)d_in[5];
    const float* pv_v         = (const float*)d_in[6];
    const float* olm_v        = (const float*)d_in[7];
    const float* bist_v       = (const float*)d_in[8];
    const float* pv_adapt     = (const float*)d_in[9];
    const float* olm_adapt    = (const float*)d_in[10];
    const float* bist_adapt   = (const float*)d_in[11];
    const float* pyr_to_pv    = (const float*)d_in[12];
    const float* pyr_to_olm   = (const float*)d_in[13];
    const float* pyr_to_bist  = (const float*)d_in[14];
    const float* pv_to_pyr    = (const float*)d_in[15];
    const float* pv_to_pyr_gb = (const float*)d_in[16];
    const float* olm_to_pyr   = (const float*)d_in[17];
    const float* bist_to_pyr  = (const float*)d_in[18];
    const float* pv_to_pv     = (const float*)d_in[19];
    const float* olm_to_pv    = (const float*)d_in[20];
    const float* pv_gap       = (const float*)d_in[21];
    const float* sept_to_olm  = (const float*)d_in[22];
    float* out = (float*)d_out;

    k_phaseA<<<13200, 256>>>(pyr_to_pv, pyr_to_olm, pyr_to_bist, pyr_spikes,
                             pv_to_pv, prev_pv_spk, olm_to_pv, prev_olm_spk,
                             pv_gap, prev_pv_vm, sept_to_olm, septal_gaba);
    k_means<<<1, 256>>>(external_exc);
    k_lif<<<(5100 + 255) / 256, 256>>>(pv_v, olm_v, bist_v,
                                       pv_adapt, olm_adapt, bist_adapt, out);
    k_out<<<5000, 256>>>(pv_to_pyr, pv_to_pyr_gb, olm_to_pyr, bist_to_pyr, out);
}

// round 3
// speedup vs baseline: 1.1253x; 1.1253x over previous
#include <cuda_runtime.h>
#include <cstddef>

#define PYR    40000
#define N_PV    2100
#define N_OLM   1800
#define N_BIST  1200
#define N_SEPT   100

// ---- device scratch (no allocations allowed) ----
__device__ float g_pv_raw[N_PV];
__device__ float g_olm_raw[N_OLM];
__device__ float g_bist_raw[N_BIST];
__device__ float g_pv_lat[N_PV];
__device__ float g_olm2pv[N_PV];
__device__ float g_gap[N_PV];
__device__ float g_olm_inh[N_OLM];
__device__ float g_scalars[2];   // [0]=ext_mean, [1]=gain

// ------------------------------------------------------------------
__device__ __forceinline__ float warpReduce(float v) {
    #pragma unroll
    for (int o = 16; o; o >>= 1) v += __shfl_xor_sync(0xffffffffu, v, o);
    return v;
}

// block-wide reduction (256 threads). Result valid on thread 0.
__device__ __forceinline__ float blockReduce256(float v) {
    __shared__ float red[8];
    int lane = threadIdx.x & 31, w = threadIdx.x >> 5;
    v = warpReduce(v);
    if (lane == 0) red[w] = v;
    __syncthreads();
    if (w == 0) {
        v = (lane < 8) ? red[lane] : 0.f;
        v = warpReduce(v);
    }
    return v;
}

// dense block dot: w[0..n) . x[0..n), n % 4 == 0
__device__ __forceinline__ float blockDotF(const float* __restrict__ w,
                                           const float* __restrict__ x, int n) {
    float s = 0.f;
    int n4 = n >> 2;
    const float4* w4 = (const float4*)w;
    const float4* x4 = (const float4*)x;
    for (int i = threadIdx.x; i < n4; i += 256) {
        float4 a = __ldcs(w4 + i);
        float4 b = __ldg(x4 + i);
        s += a.x * b.x + a.y * b.y + a.z * b.z + a.w * b.w;
    }
    return blockReduce256(s);
}

// dot against an int32 0/1 spike vector
__device__ __forceinline__ float blockDotSpk(const float* __restrict__ w,
                                             const int* __restrict__ spk, int n) {
    float s = 0.f;
    int n4 = n >> 2;
    const float4* w4 = (const float4*)w;
    const int4*   s4 = (const int4*)spk;
    #pragma unroll 4
    for (int i = threadIdx.x; i < n4; i += 256) {
        float4 a = __ldcs(w4 + i);
        int4   b = __ldg(s4 + i);
        s += (b.x ? a.x : 0.f) + (b.y ? a.y : 0.f) + (b.z ? a.z : 0.f) + (b.w ? a.w : 0.f);
    }
    return blockReduce256(s);
}

// ------------------------------------------------------------------
// Phase A: all input-side matvecs. One block per output row.
__global__ void k_phaseA(const float* __restrict__ pyr2pv,
                         const float* __restrict__ pyr2olm,
                         const float* __restrict__ pyr2bist,
                         const int*   __restrict__ pyr_spk,
                         const float* __restrict__ pv2pv,
                         const float* __restrict__ prev_pv,
                         const float* __restrict__ olm2pv,
                         const float* __restrict__ prev_olm,
                         const float* __restrict__ gapW,
                         const float* __restrict__ prev_vm,
                         const float* __restrict__ sept2olm,
                         const float* __restrict__ septal) {
    int b = blockIdx.x;
    float r;
    if (b < N_PV) {
        r = blockDotSpk(pyr2pv + (size_t)b * PYR, pyr_spk, PYR);
        if (threadIdx.x == 0) g_pv_raw[b] = r;
    } else if (b < N_PV + N_OLM) {
        int j = b - N_PV;
        r = blockDotSpk(pyr2olm + (size_t)j * PYR, pyr_spk, PYR);
        if (threadIdx.x == 0) g_olm_raw[j] = r;
    } else if (b < 5100) {
        int j = b - 3900;
        r = blockDotSpk(pyr2bist + (size_t)j * PYR, pyr_spk, PYR);
        if (threadIdx.x == 0) g_bist_raw[j] = r;
    } else if (b < 7200) {
        int j = b - 5100;
        r = blockDotF(pv2pv + (size_t)j * N_PV, prev_pv, N_PV);
        if (threadIdx.x == 0) g_pv_lat[j] = r;
    } else if (b < 9300) {
        int j = b - 7200;
        r = blockDotF(olm2pv + (size_t)j * N_OLM, prev_olm, N_OLM);
        if (threadIdx.x == 0) g_olm2pv[j] = r;
    } else if (b < 11400) {
        int j = b - 9300;
        r = blockDotF(gapW + (size_t)j * N_PV, prev_vm, N_PV);
        if (threadIdx.x == 0) g_gap[j] = r;
    } else {
        int j = b - 11400;
        r = blockDotF(sept2olm + (size_t)j * N_SEPT, septal, N_SEPT);
        if (threadIdx.x == 0) g_olm_inh[j] = r;
    }
}

// ------------------------------------------------------------------
__global__ void k_means(const float* __restrict__ ext) {
    __shared__ float redA[8], redB[8];
    float s1 = 0.f, s2 = 0.f;
    for (int i = threadIdx.x; i < N_PV; i += 256) {
        s1 += ext[i];
        s2 += g_pv_raw[i];
    }
    int lane = threadIdx.x & 31, w = threadIdx.x >> 5;
    s1 = warpReduce(s1);
    s2 = warpReduce(s2);
    if (lane == 0) { redA[w] = s1; redB[w] = s2; }
    __syncthreads();
    if (threadIdx.x == 0) {
        float t1 = 0.f, t2 = 0.f;
        #pragma unroll
        for (int i = 0; i < 8; i++) { t1 += redA[i]; t2 += redB[i]; }
        float ext_mean = t1 / (float)N_PV;
        float drive    = t2 / (float)N_PV;
        float gain = (drive > 0.01f) ? fminf(1.f, drive * 10.f) : 0.f;
        g_scalars[0] = ext_mean;
        g_scalars[1] = gain;
    }
}

// ------------------------------------------------------------------
// LIF updates; spikes written directly into output tail.
__global__ void k_lif(const float* __restrict__ pv_v,
                      const float* __restrict__ olm_v,
                      const float* __restrict__ bist_v,
                      const float* __restrict__ pv_ad,
                      const float* __restrict__ olm_ad,
                      const float* __restrict__ bist_ad,
                      float* __restrict__ out) {
    int i = blockIdx.x * blockDim.x + threadIdx.x;
    float ext_mean = g_scalars[0];
    float gain     = g_scalars[1];
    if (i < N_PV) {
        float g = g_pv_raw[i] + ext_mean * 0.3f
                - g_pv_lat[i] * 0.5f - g_olm2pv[i] * 0.3f
                + g_gap[i] * 0.05f * gain;
        g = fmaxf(g, 0.f);
        float v = pv_v[i];
        float vn = v + (1.f / 7.f) * (-v + g * (3.0f - v));
        out[160000 + i] = (vn >= 2.0f + pv_ad[i]) ? 1.f : 0.f;
    } else if (i < N_PV + N_OLM) {
        int j = i - N_PV;
        float g = fmaxf(g_olm_raw[j] + ext_mean * 0.1f, 0.f);
        float gi = g_olm_inh[j];
        float v = olm_v[j];
        float vn = v + (1.f / 25.f) * (-v + g * (3.0f - v) + gi * (-0.5f - v));
        out[162100 + j] = (vn >= 1.1f + olm_ad[j]) ? 1.f : 0.f;
    } else if (i < 5100) {
        int j = i - 3900;
        float g = fmaxf(g_bist_raw[j] + ext_mean * 0.2f, 0.f);
        float v = bist_v[j];
        float vn = v + (1.f / 12.f) * (-v + g * (3.0f - v));
        out[163900 + j] = (vn >= 0.9f + bist_ad[j]) ? 1.f : 0.f;
    }
}

// ------------------------------------------------------------------
// Output projections: warp-per-pyr-row, fused dual-stream dots for MLP.
__global__ void k_out(const float* __restrict__ pv2pyr,
                      const float* __restrict__ gabab,
                      const float* __restrict__ olm2pyr,
                      const float* __restrict__ bist2pyr,
                      float* __restrict__ out) {
    __shared__ float sh[5104];   // pv | olm | bist spikes
    for (int i = threadIdx.x; i < 5100; i += 256) sh[i] = out[160000 + i];
    __syncthreads();
    int warp = threadIdx.x >> 5;
    int lane = threadIdx.x & 31;
    int row  = blockIdx.x * 8 + warp;
    if (row >= PYR) return;

    // ---- pv + gaba_b fused (both length 2100 = 525 float4) ----
    const float4* w1 = (const float4*)(pv2pyr + (size_t)row * N_PV);
    const float4* w2 = (const float4*)(gabab  + (size_t)row * N_PV);
    const float4* xp = (const float4*)sh;
    float s1 = 0.f, s2 = 0.f;
    #pragma unroll 4
    for (int i = lane; i < 525; i += 32) {
        float4 a = __ldcs(w1 + i);
        float4 b = __ldcs(w2 + i);
        float4 c = xp[i];
        s1 += a.x * c.x + a.y * c.y + a.z * c.z + a.w * c.w;
        s2 += b.x * c.x + b.y * c.y + b.z * c.z + b.w * c.w;
    }

    // ---- olm (450 float4) + bist (300 float4) fused ----
    const float4* w3 = (const float4*)(olm2pyr  + (size_t)row * N_OLM);
    const float4* w4 = (const float4*)(bist2pyr + (size_t)row * N_BIST);
    const float4* xo = (const float4*)(sh + N_PV);
    const float4* xb = (const float4*)(sh + N_PV + N_OLM);
    float s3 = 0.f, s4 = 0.f;
    #pragma unroll 4
    for (int i = lane; i < 450; i += 32) {
        float4 a = __ldcs(w3 + i);
        float4 c = xo[i];
        s3 += a.x * c.x + a.y * c.y + a.z * c.z + a.w * c.w;
        if (i < 300) {
            float4 b = __ldcs(w4 + i);
            float4 d = xb[i];
            s4 += b.x * d.x + b.y * d.y + b.z * d.z + b.w * d.w;
        }
    }

    s1 = warpReduce(s1);
    s2 = warpReduce(s2);
    s3 = warpReduce(s3);
    s4 = warpReduce(s4);
    if (lane == 0) {
        out[row]          = s1;
        out[40000 + row]  = s2;
        out[80000 + row]  = s3 + s4;
        out[120000 + row] = s3;
    }
}

// ------------------------------------------------------------------
extern "C" void kernel_launch(void* const* d_in, const int* in_sizes, int n_in,
                              void* d_out, int out_size) {
    const int*   pyr_spikes   = (const int*)  d_in[0];
    const float* septal_gaba  = (const float*)d_in[1];
    const float* external_exc = (const float*)d_in[2];
    const float* prev_pv_spk  = (const float*)d_in[3];
    const float* prev_olm_spk = (const float*)d_in[4];
    const float* prev_pv_vm   = (const float*)d_in[5];
    const float* pv_v         = (const float*)d_in[6];
    const float* olm_v        = (const float*)d_in[7];
    const float* bist_v       = (const float*)d_in[8];
    const float* pv_adapt     = (const float*)d_in[9];
    const float* olm_adapt    = (const float*)d_in[10];
    const float* bist_adapt   = (const float*)d_in[11];
    const float* pyr_to_pv    = (const float*)d_in[12];
    const float* pyr_to_olm   = (const float*)d_in[13];
    const float* pyr_to_bist  = (const float*)d_in[14];
    const float* pv_to_pyr    = (const float*)d_in[15];
    const float* pv_to_pyr_gb = (const float*)d_in[16];
    const float* olm_to_pyr   = (const float*)d_in[17];
    const float* bist_to_pyr  = (const float*)d_in[18];
    const float* pv_to_pv     = (const float*)d_in[19];
    const float* olm_to_pv    = (const float*)d_in[20];
    const float* pv_gap       = (const float*)d_in[21];
    const float* sept_to_olm  = (const float*)d_in[22];
    float* out = (float*)d_out;

    k_phaseA<<<13200, 256>>>(pyr_to_pv, pyr_to_olm, pyr_to_bist, pyr_spikes,
                             pv_to_pv, prev_pv_spk, olm_to_pv, prev_olm_spk,
                             pv_gap, prev_pv_vm, sept_to_olm, septal_gaba);
    k_means<<<1, 256>>>(external_exc);
    k_lif<<<(5100 + 255) / 256, 256>>>(pv_v, olm_v, bist_v,
                                       pv_adapt, olm_adapt, bist_adapt, out);
    k_out<<<5000, 256>>>(pv_to_pyr, pv_to_pyr_gb, olm_to_pyr, bist_to_pyr, out);
}